// round 1
// baseline (speedup 1.0000x reference)
#include <cuda_runtime.h>
#include <cuda_bf16.h>
#include <math.h>

// Problem shape (fixed by the dataset)
#define BATCH 2
#define SEQ   2048
#define DDIM  1024
#define NHEAD 16
#define DK    64
#define MTOT  (BATCH*SEQ)   // 4096

// Scratch (device globals — no allocation allowed)
__device__ float g_q[MTOT*DDIM];
__device__ float g_k[MTOT*DDIM];
__device__ float g_v[MTOT*DDIM];
__device__ float g_o[MTOT*DDIM];

// ---------------------------------------------------------------------------
// SGEMM  C[M,N] = A[M,K] * B[N,K]^T   (both row-major, i.e. C = A * B^T)
// BM=BN=128, BK=16, 256 threads, 8x8 per thread micro-tile.
// M=4096, N=K=1024 hardcoded.
// ---------------------------------------------------------------------------
#define GBM 128
#define GBN 128
#define GBK 16
#define GPAD 4

__device__ __forceinline__ void gemm_body(const float* __restrict__ A,
                                          const float* __restrict__ B,
                                          float* __restrict__ C)
{
    const int K = DDIM;
    const int N = DDIM;

    __shared__ float As[GBK][GBM + GPAD];
    __shared__ float Bs[GBK][GBN + GPAD];

    const int tid = threadIdx.x;
    const int tx = tid & 15;        // 0..15  (cols)
    const int ty = tid >> 4;        // 0..15  (rows)
    const int row0 = blockIdx.y * GBM;
    const int col0 = blockIdx.x * GBN;

    float acc[8][8];
#pragma unroll
    for (int i = 0; i < 8; i++)
#pragma unroll
        for (int j = 0; j < 8; j++) acc[i][j] = 0.f;

    for (int k0 = 0; k0 < K; k0 += GBK) {
        // Load A tile: 128 rows x 16 cols = 512 float4 -> 2 per thread
#pragma unroll
        for (int l = 0; l < 2; l++) {
            int v  = tid + l * 256;
            int r  = v >> 2;
            int c4 = v & 3;
            float4 f = *reinterpret_cast<const float4*>(A + (size_t)(row0 + r) * K + k0 + c4 * 4);
            As[c4*4+0][r] = f.x;
            As[c4*4+1][r] = f.y;
            As[c4*4+2][r] = f.z;
            As[c4*4+3][r] = f.w;
        }
        // Load B tile (weights, row-major [N,K])
#pragma unroll
        for (int l = 0; l < 2; l++) {
            int v  = tid + l * 256;
            int r  = v >> 2;
            int c4 = v & 3;
            float4 f = *reinterpret_cast<const float4*>(B + (size_t)(col0 + r) * K + k0 + c4 * 4);
            Bs[c4*4+0][r] = f.x;
            Bs[c4*4+1][r] = f.y;
            Bs[c4*4+2][r] = f.z;
            Bs[c4*4+3][r] = f.w;
        }
        __syncthreads();

#pragma unroll
        for (int k = 0; k < GBK; k++) {
            float a[8], b[8];
#pragma unroll
            for (int i = 0; i < 8; i++) a[i] = As[k][ty*8 + i];
#pragma unroll
            for (int j = 0; j < 8; j++) b[j] = Bs[k][tx*8 + j];
#pragma unroll
            for (int i = 0; i < 8; i++)
#pragma unroll
                for (int j = 0; j < 8; j++)
                    acc[i][j] = fmaf(a[i], b[j], acc[i][j]);
        }
        __syncthreads();
    }

#pragma unroll
    for (int i = 0; i < 8; i++) {
        float* crow = C + (size_t)(row0 + ty*8 + i) * N + col0 + tx*8;
#pragma unroll
        for (int j = 0; j < 8; j += 4) {
            float4 f = make_float4(acc[i][j], acc[i][j+1], acc[i][j+2], acc[i][j+3]);
            *reinterpret_cast<float4*>(crow + j) = f;
        }
    }
}

__global__ __launch_bounds__(256)
void sgemm_qkv_kernel(const float* __restrict__ X,
                      const float* __restrict__ Wq,
                      const float* __restrict__ Wk,
                      const float* __restrict__ Wv)
{
    const float* W = (blockIdx.z == 0) ? Wq : (blockIdx.z == 1) ? Wk : Wv;
    float*       C = (blockIdx.z == 0) ? g_q : (blockIdx.z == 1) ? g_k : g_v;
    gemm_body(X, W, C);
}

__global__ __launch_bounds__(256)
void sgemm_out_kernel(const float* __restrict__ Wo, float* __restrict__ Out)
{
    gemm_body(g_o, Wo, Out);
}

// ---------------------------------------------------------------------------
// RoPE (in-place on g_q and g_k). One thread per (tensor-selected) pair.
// Per tensor: B*S*H*32 = 2^21 pairs. grid = (8192, 2), block = 256.
// ---------------------------------------------------------------------------
__global__ __launch_bounds__(256)
void rope_kernel(const int* __restrict__ pos)
{
    int id = blockIdx.x * blockDim.x + threadIdx.x;   // 0 .. 2^21-1
    float* T = (blockIdx.y == 0) ? g_q : g_k;

    int p = id & 31;            // pair index within head (0..31)
    int h = (id >> 5) & 15;     // head
    int s = (id >> 9) & 2047;   // sequence position
    int b = id >> 20;           // batch

    size_t base = ((size_t)(b * SEQ + s)) * DDIM + h * DK + 2 * p;

    // inv_freq = 10000^(-p/32) = 2^(-p * log2(10000)/32)
    float inv = exp2f(-(float)p * (13.287712379549449f / 32.0f));
    float ang = (float)pos[s] * inv;
    float sn, cs;
    sincosf(ang, &sn, &cs);     // accurate range reduction (angles up to ~2047 rad)

    float xe = T[base];
    float xo = T[base + 1];
    T[base]     = cs * xe - sn * xo;
    T[base + 1] = sn * xe + cs * xo;
}

// ---------------------------------------------------------------------------
// Causal flash attention, fp32.
// Block = 64 threads; each thread owns one query row (q, o in registers).
// K/V tiles (64x64) in shared, scores staged per-thread in shared row.
// grid = (S/64 = 32, B*H = 32)
// ---------------------------------------------------------------------------
__global__ __launch_bounds__(64)
void attn_kernel()
{
    __shared__ float Ks[64][64];
    __shared__ float Vs[64][64];
    __shared__ float Sb[64][65];   // padded: thread-private score rows

    const int t  = threadIdx.x;
    const int qt = blockIdx.x;          // query tile 0..31
    const int bh = blockIdx.y;          // 0..31
    const int b  = bh >> 4;
    const int h  = bh & 15;
    const int qi = qt * 64 + t;
    const float scale = 0.125f;         // 1/sqrt(64)

    const size_t base = (size_t)b * SEQ * DDIM + h * DK;

    float qreg[64];
    {
        const float* qptr = g_q + base + (size_t)qi * DDIM;
#pragma unroll
        for (int d = 0; d < 64; d++) qreg[d] = qptr[d] * scale;
    }

    float m = -1e30f, l = 0.f;
    float o[64];
#pragma unroll
    for (int d = 0; d < 64; d++) o[d] = 0.f;

    for (int kt = 0; kt <= qt; kt++) {
        const int j0 = kt * 64;
        // cooperative tile load: iteration it loads row (j0+it), col t (coalesced)
#pragma unroll 8
        for (int it = 0; it < 64; it++) {
            size_t g = base + (size_t)(j0 + it) * DDIM + t;
            Ks[it][t] = g_k[g];
            Vs[it][t] = g_v[g];
        }
        __syncthreads();

        const bool diag = (kt == qt);
        float tmax = -1e30f;
#pragma unroll 4
        for (int j = 0; j < 64; j++) {
            float s = 0.f;
#pragma unroll
            for (int d = 0; d < 64; d++) s = fmaf(qreg[d], Ks[j][d], s);
            if (diag && (j0 + j) > qi) s = -1e30f;
            Sb[t][j] = s;
            tmax = fmaxf(tmax, s);
        }

        float mnew  = fmaxf(m, tmax);
        float alpha = __expf(m - mnew);
        l *= alpha;
#pragma unroll
        for (int d = 0; d < 64; d++) o[d] *= alpha;

#pragma unroll 2
        for (int j = 0; j < 64; j++) {
            float p = __expf(Sb[t][j] - mnew);
            l += p;
#pragma unroll
            for (int d = 0; d < 64; d++) o[d] = fmaf(p, Vs[j][d], o[d]);
        }
        m = mnew;
        __syncthreads();
    }

    const float inv_l = 1.0f / l;
    float* optr = g_o + base + (size_t)qi * DDIM;
#pragma unroll
    for (int d = 0; d < 64; d++) optr[d] = o[d] * inv_l;
}

// ---------------------------------------------------------------------------
extern "C" void kernel_launch(void* const* d_in, const int* in_sizes, int n_in,
                              void* d_out, int out_size)
{
    const float* x  = (const float*)d_in[0];
    const int*   tp = (const int*)  d_in[1];
    const float* wq = (const float*)d_in[2];
    const float* wk = (const float*)d_in[3];
    const float* wv = (const float*)d_in[4];
    const float* wo = (const float*)d_in[5];
    float* out = (float*)d_out;

    // QKV projections: C[M=4096, N=1024] per weight
    dim3 gqkv(DDIM / GBN, MTOT / GBM, 3);      // (8, 32, 3)
    sgemm_qkv_kernel<<<gqkv, 256>>>(x, wq, wk, wv);

    // RoPE on q and k
    rope_kernel<<<dim3(8192, 2), 256>>>(tp);

    // Causal attention
    attn_kernel<<<dim3(SEQ / 64, BATCH * NHEAD), 64>>>();

    // Output projection
    dim3 gout(DDIM / GBN, MTOT / GBM, 1);
    sgemm_out_kernel<<<gout, 256>>>(wo, out);
}

// round 3
// speedup vs baseline: 2.6695x; 2.6695x over previous
#include <cuda_runtime.h>
#include <cuda_bf16.h>
#include <math.h>
#include <stdint.h>

// Problem shape (fixed)
#define BATCH 2
#define SEQ   2048
#define DDIM  1024
#define NHEAD 16
#define DK    64
#define MTOT  (BATCH*SEQ)   // 4096

// ---------------------------------------------------------------------------
// Device-global scratch
// ---------------------------------------------------------------------------
__device__ float g_q[MTOT*DDIM];
__device__ float g_k[MTOT*DDIM];
__device__ float g_v[MTOT*DDIM];
__device__ float g_o[MTOT*DDIM];

__device__ __nv_bfloat16 g_xhi[MTOT*DDIM];
__device__ __nv_bfloat16 g_xlo[MTOT*DDIM];
__device__ __nv_bfloat16 g_ohi[MTOT*DDIM];
__device__ __nv_bfloat16 g_olo[MTOT*DDIM];
__device__ __nv_bfloat16 g_whi[4*DDIM*DDIM];
__device__ __nv_bfloat16 g_wlo[4*DDIM*DDIM];

// ---------------------------------------------------------------------------
// HMMA helper: D(16x8,f32) += A(16x16,bf16,row) * B(16x8,bf16,col)
// ---------------------------------------------------------------------------
__device__ __forceinline__ void mma16816(float* d, const uint32_t* a, const uint32_t* b)
{
    asm volatile(
        "mma.sync.aligned.m16n8k16.row.col.f32.bf16.bf16.f32 "
        "{%0,%1,%2,%3}, {%4,%5,%6,%7}, {%8,%9}, {%0,%1,%2,%3};"
        : "+f"(d[0]), "+f"(d[1]), "+f"(d[2]), "+f"(d[3])
        : "r"(a[0]), "r"(a[1]), "r"(a[2]), "r"(a[3]), "r"(b[0]), "r"(b[1]));
}

__device__ __forceinline__ uint32_t pack_bf16(float f0, float f1)
{
    __nv_bfloat162 t = __floats2bfloat162_rn(f0, f1);
    return *reinterpret_cast<uint32_t*>(&t);
}

// ---------------------------------------------------------------------------
// Split-bf16 HMMA GEMM: C[M,N] = A[M,K]*B[N,K]^T, 3-term (hh + hl + lh)
// CTA 128x128, 8 warps (2m x 4n -> 64x32 warp tile), kc=32.
// ---------------------------------------------------------------------------
#define SAS 40   // smem row stride in bf16 elems (32 + 8 pad)

__device__ __forceinline__ void hmma_gemm_body(
    const __nv_bfloat16* __restrict__ Ahi, const __nv_bfloat16* __restrict__ Alo,
    const __nv_bfloat16* __restrict__ Bhi, const __nv_bfloat16* __restrict__ Blo,
    float* __restrict__ C, int row0, int col0)
{
    __shared__ __nv_bfloat16 sAhi[128*SAS], sAlo[128*SAS];
    __shared__ __nv_bfloat16 sBhi[128*SAS], sBlo[128*SAS];

    const int tid  = threadIdx.x;
    const int warp = tid >> 5;
    const int lane = tid & 31;
    const int g    = lane >> 2;
    const int tig  = lane & 3;
    const int wm   = warp >> 2;       // 0..1
    const int wn   = warp & 3;        // 0..3
    const int wr0  = wm * 64;
    const int wc0  = wn * 32;

    float acc[4][4][4];
#pragma unroll
    for (int i = 0; i < 4; i++)
#pragma unroll
        for (int j = 0; j < 4; j++)
#pragma unroll
            for (int r = 0; r < 4; r++) acc[i][j][r] = 0.f;

    for (int k0 = 0; k0 < DDIM; k0 += 32) {
        // Load tiles: each array 128 rows x 32 bf16 = 512 uint4; 2 per thread
#pragma unroll
        for (int l = 0; l < 2; l++) {
            int idx = tid + l * 256;
            int r = idx >> 2;
            int c = idx & 3;            // 16B units
            size_t ga = (size_t)(row0 + r) * DDIM + k0 + c * 8;
            size_t gb = (size_t)(col0 + r) * DDIM + k0 + c * 8;
            int so = r * SAS + c * 8;
            *reinterpret_cast<uint4*>(&sAhi[so]) = *reinterpret_cast<const uint4*>(Ahi + ga);
            *reinterpret_cast<uint4*>(&sAlo[so]) = *reinterpret_cast<const uint4*>(Alo + ga);
            *reinterpret_cast<uint4*>(&sBhi[so]) = *reinterpret_cast<const uint4*>(Bhi + gb);
            *reinterpret_cast<uint4*>(&sBlo[so]) = *reinterpret_cast<const uint4*>(Blo + gb);
        }
        __syncthreads();

#pragma unroll
        for (int ks = 0; ks < 2; ks++) {
            const int kc = ks * 16 + 2 * tig;
            uint32_t bh[4][2], bl[4][2];
#pragma unroll
            for (int ni = 0; ni < 4; ni++) {
                const __nv_bfloat16* bp = &sBhi[(wc0 + ni*8 + g) * SAS + kc];
                const __nv_bfloat16* lp = &sBlo[(wc0 + ni*8 + g) * SAS + kc];
                bh[ni][0] = *reinterpret_cast<const uint32_t*>(bp);
                bh[ni][1] = *reinterpret_cast<const uint32_t*>(bp + 8);
                bl[ni][0] = *reinterpret_cast<const uint32_t*>(lp);
                bl[ni][1] = *reinterpret_cast<const uint32_t*>(lp + 8);
            }
#pragma unroll
            for (int mi = 0; mi < 4; mi++) {
                const __nv_bfloat16* ap = &sAhi[(wr0 + mi*16 + g) * SAS + kc];
                const __nv_bfloat16* lp = &sAlo[(wr0 + mi*16 + g) * SAS + kc];
                uint32_t ah[4], al[4];
                ah[0] = *reinterpret_cast<const uint32_t*>(ap);
                ah[1] = *reinterpret_cast<const uint32_t*>(ap + 8*SAS);
                ah[2] = *reinterpret_cast<const uint32_t*>(ap + 8);
                ah[3] = *reinterpret_cast<const uint32_t*>(ap + 8*SAS + 8);
                al[0] = *reinterpret_cast<const uint32_t*>(lp);
                al[1] = *reinterpret_cast<const uint32_t*>(lp + 8*SAS);
                al[2] = *reinterpret_cast<const uint32_t*>(lp + 8);
                al[3] = *reinterpret_cast<const uint32_t*>(lp + 8*SAS + 8);
#pragma unroll
                for (int ni = 0; ni < 4; ni++) {
                    mma16816(acc[mi][ni], ah, bh[ni]);
                    mma16816(acc[mi][ni], ah, bl[ni]);
                    mma16816(acc[mi][ni], al, bh[ni]);
                }
            }
        }
        __syncthreads();
    }

    // Epilogue
#pragma unroll
    for (int mi = 0; mi < 4; mi++) {
#pragma unroll
        for (int ni = 0; ni < 4; ni++) {
            int r = row0 + wr0 + mi*16 + g;
            int c = col0 + wc0 + ni*8 + 2*tig;
            *reinterpret_cast<float2*>(&C[(size_t)r * DDIM + c]) =
                make_float2(acc[mi][ni][0], acc[mi][ni][1]);
            *reinterpret_cast<float2*>(&C[(size_t)(r + 8) * DDIM + c]) =
                make_float2(acc[mi][ni][2], acc[mi][ni][3]);
        }
    }
}

__global__ __launch_bounds__(256)
void qkv_hmma_kernel()
{
    const int z = blockIdx.z;
    float* C = (z == 0) ? g_q : (z == 1) ? g_k : g_v;
    const size_t wo = (size_t)z * DDIM * DDIM;
    hmma_gemm_body(g_xhi, g_xlo, g_whi + wo, g_wlo + wo, C,
                   blockIdx.y * 128, blockIdx.x * 128);
}

__global__ __launch_bounds__(256)
void out_hmma_kernel(float* __restrict__ Out)
{
    const size_t wo = 3ull * DDIM * DDIM;
    hmma_gemm_body(g_ohi, g_olo, g_whi + wo, g_wlo + wo, Out,
                   blockIdx.y * 128, blockIdx.x * 128);
}

// ---------------------------------------------------------------------------
// fp32 -> (bf16 hi, bf16 lo) split kernels
// ---------------------------------------------------------------------------
__device__ __forceinline__ void split4_store(const float4 v,
                                             __nv_bfloat16* hi, __nv_bfloat16* lo, size_t i)
{
    float f[4] = {v.x, v.y, v.z, v.w};
    unsigned short H[4], L[4];
#pragma unroll
    for (int j = 0; j < 4; j++) {
        __nv_bfloat16 h = __float2bfloat16_rn(f[j]);
        __nv_bfloat16 l = __float2bfloat16_rn(f[j] - __bfloat162float(h));
        H[j] = __bfloat16_as_ushort(h);
        L[j] = __bfloat16_as_ushort(l);
    }
    reinterpret_cast<ushort4*>(hi)[i] = make_ushort4(H[0], H[1], H[2], H[3]);
    reinterpret_cast<ushort4*>(lo)[i] = make_ushort4(L[0], L[1], L[2], L[3]);
}

__global__ __launch_bounds__(256)
void split_x_kernel(const float* __restrict__ in,
                    __nv_bfloat16* __restrict__ hi, __nv_bfloat16* __restrict__ lo)
{
    size_t i = (size_t)blockIdx.x * 256 + threadIdx.x;
    float4 v = reinterpret_cast<const float4*>(in)[i];
    split4_store(v, hi, lo, i);
}

__global__ __launch_bounds__(256)
void split_w_kernel(const float* __restrict__ wq, const float* __restrict__ wk,
                    const float* __restrict__ wv, const float* __restrict__ wo)
{
    const int z = blockIdx.z;
    const float* src = (z == 0) ? wq : (z == 1) ? wk : (z == 2) ? wv : wo;
    __nv_bfloat16* hi = g_whi + (size_t)z * DDIM * DDIM;
    __nv_bfloat16* lo = g_wlo + (size_t)z * DDIM * DDIM;
    size_t i = (size_t)blockIdx.x * 256 + threadIdx.x;
    float4 v = reinterpret_cast<const float4*>(src)[i];
    split4_store(v, hi, lo, i);
}

// ---------------------------------------------------------------------------
// RoPE (in-place on g_q and g_k)
// ---------------------------------------------------------------------------
__global__ __launch_bounds__(256)
void rope_kernel(const int* __restrict__ pos)
{
    int id = blockIdx.x * blockDim.x + threadIdx.x;
    float* T = (blockIdx.y == 0) ? g_q : g_k;

    int p = id & 31;
    int h = (id >> 5) & 15;
    int s = (id >> 9) & 2047;
    int b = id >> 20;

    size_t base = ((size_t)(b * SEQ + s)) * DDIM + h * DK + 2 * p;

    float inv = exp2f(-(float)p * (13.287712379549449f / 32.0f));
    float ang = (float)pos[s] * inv;
    float sn, cs;
    sincosf(ang, &sn, &cs);

    float xe = T[base];
    float xo = T[base + 1];
    T[base]     = cs * xe - sn * xo;
    T[base + 1] = sn * xe + cs * xo;
}

// ---------------------------------------------------------------------------
// Flash attention with HMMA, split-bf16 3-term for QK^T and PV.
// CTA: 128 query rows, 256 threads (8 warps x 16 rows). Key tiles of 64.
// ---------------------------------------------------------------------------
#define AST 72                    // smem row stride (64 + 8 pad), bf16 elems
#define A_QHI 0
#define A_QLO (A_QHI + 128*AST)   // 9216
#define A_KHI (A_QLO + 128*AST)   // 18432
#define A_KLO (A_KHI + 64*AST)    // 23040
#define A_VHI (A_KLO + 64*AST)    // 27648 (transposed: [d][key])
#define A_VLO (A_VHI + 64*AST)    // 32256
#define ATT_SMEM ((A_VLO + 64*AST) * 2)   // 73728 bytes

__global__ __launch_bounds__(256)
void attn_hmma_kernel()
{
    extern __shared__ __nv_bfloat16 sm[];
    __nv_bfloat16* sQhi = sm + A_QHI;
    __nv_bfloat16* sQlo = sm + A_QLO;
    __nv_bfloat16* sKhi = sm + A_KHI;
    __nv_bfloat16* sKlo = sm + A_KLO;
    __nv_bfloat16* sVhi = sm + A_VHI;
    __nv_bfloat16* sVlo = sm + A_VLO;

    const int tid  = threadIdx.x;
    const int warp = tid >> 5;
    const int lane = tid & 31;
    const int g    = lane >> 2;
    const int tig  = lane & 3;

    const int q0 = blockIdx.x * 128;
    const int bh = blockIdx.y;
    const int b  = bh >> 4;
    const int h  = bh & 15;
    const size_t gbase = (size_t)b * SEQ * DDIM + h * DK;

    // Load + scale + split Q tile (128 x 64)
#pragma unroll
    for (int l = 0; l < 32; l++) {
        int idx = tid + l * 256;
        int r = idx >> 6, c = idx & 63;
        float v = g_q[gbase + (size_t)(q0 + r) * DDIM + c] * 0.125f;
        __nv_bfloat16 hi = __float2bfloat16_rn(v);
        sQhi[r*AST + c] = hi;
        sQlo[r*AST + c] = __float2bfloat16_rn(v - __bfloat162float(hi));
    }

    const int r0 = warp * 16;          // warp's query rows within tile
    float m0 = -1e30f, m1 = -1e30f, l0 = 0.f, l1 = 0.f;
    float of[8][4];
#pragma unroll
    for (int ni = 0; ni < 8; ni++)
#pragma unroll
        for (int r = 0; r < 4; r++) of[ni][r] = 0.f;

    const int diag0 = q0 >> 6;
    const int ktmax = diag0 + 1;

    for (int kt = 0; kt <= ktmax; kt++) {
        __syncthreads();
        // Load + split K tile (64 x 64) and V tile transposed -> [d][key]
#pragma unroll
        for (int l = 0; l < 16; l++) {
            int idx = tid + l * 256;
            int r = idx >> 6, c = idx & 63;
            size_t ga = gbase + (size_t)(kt*64 + r) * DDIM + c;
            float kv = g_k[ga];
            __nv_bfloat16 khv = __float2bfloat16_rn(kv);
            sKhi[r*AST + c] = khv;
            sKlo[r*AST + c] = __float2bfloat16_rn(kv - __bfloat162float(khv));
            float vv = g_v[ga];
            __nv_bfloat16 vhv = __float2bfloat16_rn(vv);
            sVhi[c*AST + r] = vhv;
            sVlo[c*AST + r] = __float2bfloat16_rn(vv - __bfloat162float(vhv));
        }
        __syncthreads();

        // ---- S = Q K^T (16 x 64 per warp) ----
        float sf[8][4];
#pragma unroll
        for (int ni = 0; ni < 8; ni++)
#pragma unroll
            for (int r = 0; r < 4; r++) sf[ni][r] = 0.f;

#pragma unroll
        for (int ks = 0; ks < 4; ks++) {
            const int kc = ks * 16 + 2 * tig;
            const __nv_bfloat16* qp = &sQhi[(r0 + g)*AST + kc];
            const __nv_bfloat16* ql = &sQlo[(r0 + g)*AST + kc];
            uint32_t ah[4], al[4];
            ah[0] = *reinterpret_cast<const uint32_t*>(qp);
            ah[1] = *reinterpret_cast<const uint32_t*>(qp + 8*AST);
            ah[2] = *reinterpret_cast<const uint32_t*>(qp + 8);
            ah[3] = *reinterpret_cast<const uint32_t*>(qp + 8*AST + 8);
            al[0] = *reinterpret_cast<const uint32_t*>(ql);
            al[1] = *reinterpret_cast<const uint32_t*>(ql + 8*AST);
            al[2] = *reinterpret_cast<const uint32_t*>(ql + 8);
            al[3] = *reinterpret_cast<const uint32_t*>(ql + 8*AST + 8);
#pragma unroll
            for (int ni = 0; ni < 8; ni++) {
                const __nv_bfloat16* kp = &sKhi[(ni*8 + g)*AST + kc];
                const __nv_bfloat16* kl = &sKlo[(ni*8 + g)*AST + kc];
                uint32_t bhr[2], blr[2];
                bhr[0] = *reinterpret_cast<const uint32_t*>(kp);
                bhr[1] = *reinterpret_cast<const uint32_t*>(kp + 8);
                blr[0] = *reinterpret_cast<const uint32_t*>(kl);
                blr[1] = *reinterpret_cast<const uint32_t*>(kl + 8);
                mma16816(sf[ni], ah, bhr);
                mma16816(sf[ni], ah, blr);
                mma16816(sf[ni], al, bhr);
            }
        }

        // ---- causal mask (diagonal tiles only) ----
        if (kt >= diag0) {
            const int rowg0 = q0 + r0 + g;
#pragma unroll
            for (int ni = 0; ni < 8; ni++) {
                int c0 = kt*64 + ni*8 + 2*tig;
                if (c0     > rowg0)     sf[ni][0] = -1e30f;
                if (c0 + 1 > rowg0)     sf[ni][1] = -1e30f;
                if (c0     > rowg0 + 8) sf[ni][2] = -1e30f;
                if (c0 + 1 > rowg0 + 8) sf[ni][3] = -1e30f;
            }
        }

        // ---- online softmax ----
        float tm0 = -1e30f, tm1 = -1e30f;
#pragma unroll
        for (int ni = 0; ni < 8; ni++) {
            tm0 = fmaxf(tm0, fmaxf(sf[ni][0], sf[ni][1]));
            tm1 = fmaxf(tm1, fmaxf(sf[ni][2], sf[ni][3]));
        }
        tm0 = fmaxf(tm0, __shfl_xor_sync(0xFFFFFFFF, tm0, 1));
        tm0 = fmaxf(tm0, __shfl_xor_sync(0xFFFFFFFF, tm0, 2));
        tm1 = fmaxf(tm1, __shfl_xor_sync(0xFFFFFFFF, tm1, 1));
        tm1 = fmaxf(tm1, __shfl_xor_sync(0xFFFFFFFF, tm1, 2));

        float mn0 = fmaxf(m0, tm0);
        float mn1 = fmaxf(m1, tm1);
        float a0 = __expf(m0 - mn0);
        float a1 = __expf(m1 - mn1);
        l0 *= a0; l1 *= a1;
#pragma unroll
        for (int ni = 0; ni < 8; ni++) {
            of[ni][0] *= a0; of[ni][1] *= a0;
            of[ni][2] *= a1; of[ni][3] *= a1;
        }
#pragma unroll
        for (int ni = 0; ni < 8; ni++) {
            float p0 = __expf(sf[ni][0] - mn0);
            float p1 = __expf(sf[ni][1] - mn0);
            float p2 = __expf(sf[ni][2] - mn1);
            float p3 = __expf(sf[ni][3] - mn1);
            sf[ni][0] = p0; sf[ni][1] = p1; sf[ni][2] = p2; sf[ni][3] = p3;
            l0 += p0 + p1;  l1 += p2 + p3;
        }
        m0 = mn0; m1 = mn1;

        // ---- O += P V ----
#pragma unroll
        for (int kb = 0; kb < 4; kb++) {
            // S-frag layout == A-frag layout: no shuffles needed
            uint32_t ph[4], pl[4];
            float f00 = sf[2*kb][0],   f01 = sf[2*kb][1];
            float f10 = sf[2*kb][2],   f11 = sf[2*kb][3];
            float f20 = sf[2*kb+1][0], f21 = sf[2*kb+1][1];
            float f30 = sf[2*kb+1][2], f31 = sf[2*kb+1][3];
            ph[0] = pack_bf16(f00, f01);
            ph[1] = pack_bf16(f10, f11);
            ph[2] = pack_bf16(f20, f21);
            ph[3] = pack_bf16(f30, f31);
            float h00 = __bfloat162float(__float2bfloat16_rn(f00));
            float h01 = __bfloat162float(__float2bfloat16_rn(f01));
            float h10 = __bfloat162float(__float2bfloat16_rn(f10));
            float h11 = __bfloat162float(__float2bfloat16_rn(f11));
            float h20 = __bfloat162float(__float2bfloat16_rn(f20));
            float h21 = __bfloat162float(__float2bfloat16_rn(f21));
            float h30 = __bfloat162float(__float2bfloat16_rn(f30));
            float h31 = __bfloat162float(__float2bfloat16_rn(f31));
            pl[0] = pack_bf16(f00 - h00, f01 - h01);
            pl[1] = pack_bf16(f10 - h10, f11 - h11);
            pl[2] = pack_bf16(f20 - h20, f21 - h21);
            pl[3] = pack_bf16(f30 - h30, f31 - h31);

            const int kc = kb * 16 + 2 * tig;
#pragma unroll
            for (int ni = 0; ni < 8; ni++) {
                const __nv_bfloat16* vp = &sVhi[(ni*8 + g)*AST + kc];
                const __nv_bfloat16* vl = &sVlo[(ni*8 + g)*AST + kc];
                uint32_t vhr[2], vlr[2];
                vhr[0] = *reinterpret_cast<const uint32_t*>(vp);
                vhr[1] = *reinterpret_cast<const uint32_t*>(vp + 8);
                vlr[0] = *reinterpret_cast<const uint32_t*>(vl);
                vlr[1] = *reinterpret_cast<const uint32_t*>(vl + 8);
                mma16816(of[ni], ph, vhr);
                mma16816(of[ni], ph, vlr);
                mma16816(of[ni], pl, vhr);
            }
        }
    }

    // Final: reduce l over quad, normalize, store
    l0 += __shfl_xor_sync(0xFFFFFFFF, l0, 1);
    l0 += __shfl_xor_sync(0xFFFFFFFF, l0, 2);
    l1 += __shfl_xor_sync(0xFFFFFFFF, l1, 1);
    l1 += __shfl_xor_sync(0xFFFFFFFF, l1, 2);
    const float inv0 = 1.0f / l0;
    const float inv1 = 1.0f / l1;

    const int rowg = q0 + r0 + g;
#pragma unroll
    for (int ni = 0; ni < 8; ni++) {
        int c = ni*8 + 2*tig;
        *reinterpret_cast<float2*>(&g_o[gbase + (size_t)rowg * DDIM + c]) =
            make_float2(of[ni][0] * inv0, of[ni][1] * inv0);
        *reinterpret_cast<float2*>(&g_o[gbase + (size_t)(rowg + 8) * DDIM + c]) =
            make_float2(of[ni][2] * inv1, of[ni][3] * inv1);
    }
}

// ---------------------------------------------------------------------------
extern "C" void kernel_launch(void* const* d_in, const int* in_sizes, int n_in,
                              void* d_out, int out_size)
{
    const float* x  = (const float*)d_in[0];
    const int*   tp = (const int*)  d_in[1];
    const float* wq = (const float*)d_in[2];
    const float* wk = (const float*)d_in[3];
    const float* wv = (const float*)d_in[4];
    const float* wo = (const float*)d_in[5];
    float* out = (float*)d_out;

    cudaFuncSetAttribute(attn_hmma_kernel, cudaFuncAttributeMaxDynamicSharedMemorySize, ATT_SMEM);

    __nv_bfloat16 *xhi, *xlo, *ohi, *olo;
    float *go;
    cudaGetSymbolAddress((void**)&xhi, g_xhi);
    cudaGetSymbolAddress((void**)&xlo, g_xlo);
    cudaGetSymbolAddress((void**)&ohi, g_ohi);
    cudaGetSymbolAddress((void**)&olo, g_olo);
    cudaGetSymbolAddress((void**)&go,  g_o);

    // Split inputs to bf16 hi/lo
    split_x_kernel<<<(MTOT*DDIM/4)/256, 256>>>(x, xhi, xlo);
    split_w_kernel<<<dim3((DDIM*DDIM/4)/256, 1, 4), 256>>>(wq, wk, wv, wo);

    // QKV projections (HMMA)
    qkv_hmma_kernel<<<dim3(DDIM/128, MTOT/128, 3), 256>>>();

    // RoPE on q and k
    rope_kernel<<<dim3(8192, 2), 256>>>(tp);

    // Causal flash attention (HMMA)
    attn_hmma_kernel<<<dim3(SEQ/128, BATCH*NHEAD), 256, ATT_SMEM>>>();

    // Output projection (HMMA)
    split_x_kernel<<<(MTOT*DDIM/4)/256, 256>>>(go, ohi, olo);
    out_hmma_kernel<<<dim3(DDIM/128, MTOT/128, 1), 256>>>(out);
}

// round 4
// speedup vs baseline: 3.1905x; 1.1952x over previous
#include <cuda_runtime.h>
#include <cuda_bf16.h>
#include <math.h>
#include <stdint.h>

// Problem shape (fixed)
#define BATCH 2
#define SEQ   2048
#define DDIM  1024
#define NHEAD 16
#define DK    64
#define MTOT  (BATCH*SEQ)   // 4096

// ---------------------------------------------------------------------------
// Device-global scratch (bf16 hi/lo split everywhere; no fp32 intermediates)
// ---------------------------------------------------------------------------
__device__ __nv_bfloat16 g_xhi[MTOT*DDIM], g_xlo[MTOT*DDIM];
__device__ __nv_bfloat16 g_qhi[MTOT*DDIM], g_qlo[MTOT*DDIM];
__device__ __nv_bfloat16 g_khi[MTOT*DDIM], g_klo[MTOT*DDIM];
__device__ __nv_bfloat16 g_vhi[MTOT*DDIM], g_vlo[MTOT*DDIM];
__device__ __nv_bfloat16 g_ohi[MTOT*DDIM], g_olo[MTOT*DDIM];
__device__ __nv_bfloat16 g_whi[4*DDIM*DDIM], g_wlo[4*DDIM*DDIM];

// ---------------------------------------------------------------------------
// PTX helpers
// ---------------------------------------------------------------------------
__device__ __forceinline__ uint32_t smem_u32(const void* p) {
    uint32_t a;
    asm("{ .reg .u64 t; cvta.to.shared.u64 t, %1; cvt.u32.u64 %0, t; }"
        : "=r"(a) : "l"(p));
    return a;
}

__device__ __forceinline__ void mma16816(float* d, const uint32_t* a, const uint32_t* b)
{
    asm volatile(
        "mma.sync.aligned.m16n8k16.row.col.f32.bf16.bf16.f32 "
        "{%0,%1,%2,%3}, {%4,%5,%6,%7}, {%8,%9}, {%0,%1,%2,%3};"
        : "+f"(d[0]), "+f"(d[1]), "+f"(d[2]), "+f"(d[3])
        : "r"(a[0]), "r"(a[1]), "r"(a[2]), "r"(a[3]), "r"(b[0]), "r"(b[1]));
}

__device__ __forceinline__ void ldsm_x4_t(uint32_t* r, uint32_t saddr)
{
    asm volatile("ldmatrix.sync.aligned.m8n8.x4.trans.shared.b16 {%0,%1,%2,%3}, [%4];"
        : "=r"(r[0]), "=r"(r[1]), "=r"(r[2]), "=r"(r[3]) : "r"(saddr));
}

__device__ __forceinline__ void cp16(uint32_t saddr, const void* g) {
    asm volatile("cp.async.cg.shared.global [%0], [%1], 16;" :: "r"(saddr), "l"(g) : "memory");
}
#define CP_COMMIT() asm volatile("cp.async.commit_group;" ::: "memory")
#define CP_WAIT(n)  asm volatile("cp.async.wait_group %0;" :: "n"(n) : "memory")

__device__ __forceinline__ uint32_t pack_bf16(float f0, float f1)
{
    __nv_bfloat162 t = __floats2bfloat162_rn(f0, f1);
    return *reinterpret_cast<uint32_t*>(&t);
}

// split a float pair into bf16 hi/lo arrays (32-bit stores)
__device__ __forceinline__ void store_split2(__nv_bfloat16* hi, __nv_bfloat16* lo,
                                             size_t off, float a, float b)
{
    __nv_bfloat16 ah = __float2bfloat16_rn(a);
    __nv_bfloat16 bh = __float2bfloat16_rn(b);
    float al = a - __bfloat162float(ah);
    float bl = b - __bfloat162float(bh);
    __nv_bfloat162 hv; hv.x = ah; hv.y = bh;
    *reinterpret_cast<__nv_bfloat162*>(hi + off) = hv;
    *reinterpret_cast<__nv_bfloat162*>(lo + off) = __floats2bfloat162_rn(al, bl);
}

// ---------------------------------------------------------------------------
// Split-bf16 HMMA GEMM, cp.async double-buffered.
// C[M,N] = A[M,K]*B[N,K]^T, 3-term (hh + hl + lh). CTA 128x128, kc=32.
// MODE: 0 = rope+scale -> bf16 split (Q)     1 = rope -> bf16 split (K)
//       2 = bf16 split (V)                   3 = fp32 store (final out)
// ---------------------------------------------------------------------------
#define SAS 40                         // smem row stride (32 + 8 pad) bf16
#define G_STAGE (4*128*SAS)            // 20480 elems per stage
#define GEMM_SMEM (2*G_STAGE*2)        // 81920 bytes

__device__ __forceinline__ void gemm_issue(
    const __nv_bfloat16* Ahi, const __nv_bfloat16* Alo,
    const __nv_bfloat16* Bhi, const __nv_bfloat16* Blo,
    int row0, int col0, int k0, int st, uint32_t smb, int tid)
{
#pragma unroll
    for (int l = 0; l < 8; l++) {
        int a = l >> 1;
        int j = tid + (l & 1) * 256;
        int r = j >> 2, c = j & 3;
        const __nv_bfloat16* src = (a == 0) ? Ahi : (a == 1) ? Alo : (a == 2) ? Bhi : Blo;
        size_t go = (a < 2) ? ((size_t)(row0 + r) * DDIM + k0 + c * 8)
                            : ((size_t)(col0 + r) * DDIM + k0 + c * 8);
        uint32_t so = smb + (uint32_t)(st * G_STAGE + a * (128*SAS) + r * SAS + c * 8) * 2;
        cp16(so, src + go);
    }
}

template<int MODE>
__device__ __forceinline__ void hmma_gemm_body(
    const __nv_bfloat16* __restrict__ Ahi, const __nv_bfloat16* __restrict__ Alo,
    const __nv_bfloat16* __restrict__ Bhi, const __nv_bfloat16* __restrict__ Blo,
    float* __restrict__ C, __nv_bfloat16* __restrict__ Dhi, __nv_bfloat16* __restrict__ Dlo,
    const int* __restrict__ tp, int row0, int col0)
{
    extern __shared__ char dynsm[];
    __nv_bfloat16* sm = reinterpret_cast<__nv_bfloat16*>(dynsm);
    const uint32_t smb = smem_u32(sm);

    const int tid  = threadIdx.x;
    const int warp = tid >> 5;
    const int lane = tid & 31;
    const int g    = lane >> 2;
    const int tig  = lane & 3;
    const int wr0  = (warp >> 2) * 64;
    const int wc0  = (warp & 3) * 32;

    float acc[4][4][4];
#pragma unroll
    for (int i = 0; i < 4; i++)
#pragma unroll
        for (int j = 0; j < 4; j++)
#pragma unroll
            for (int r = 0; r < 4; r++) acc[i][j][r] = 0.f;

    gemm_issue(Ahi, Alo, Bhi, Blo, row0, col0, 0, 0, smb, tid);
    CP_COMMIT();

    for (int ch = 0; ch < 32; ch++) {
        if (ch < 31)
            gemm_issue(Ahi, Alo, Bhi, Blo, row0, col0, (ch + 1) * 32, (ch + 1) & 1, smb, tid);
        CP_COMMIT();
        if (ch < 31) { CP_WAIT(1); } else { CP_WAIT(0); }
        __syncthreads();

        const __nv_bfloat16* sAhi = sm + (ch & 1) * G_STAGE;
        const __nv_bfloat16* sAlo = sAhi + 128*SAS;
        const __nv_bfloat16* sBhi = sAlo + 128*SAS;
        const __nv_bfloat16* sBlo = sBhi + 128*SAS;

#pragma unroll
        for (int ks = 0; ks < 2; ks++) {
            const int kc = ks * 16 + 2 * tig;
            uint32_t bh[4][2], bl[4][2];
#pragma unroll
            for (int ni = 0; ni < 4; ni++) {
                const __nv_bfloat16* bp = &sBhi[(wc0 + ni*8 + g) * SAS + kc];
                const __nv_bfloat16* lp = &sBlo[(wc0 + ni*8 + g) * SAS + kc];
                bh[ni][0] = *reinterpret_cast<const uint32_t*>(bp);
                bh[ni][1] = *reinterpret_cast<const uint32_t*>(bp + 8);
                bl[ni][0] = *reinterpret_cast<const uint32_t*>(lp);
                bl[ni][1] = *reinterpret_cast<const uint32_t*>(lp + 8);
            }
#pragma unroll
            for (int mi = 0; mi < 4; mi++) {
                const __nv_bfloat16* ap = &sAhi[(wr0 + mi*16 + g) * SAS + kc];
                const __nv_bfloat16* lp = &sAlo[(wr0 + mi*16 + g) * SAS + kc];
                uint32_t ah[4], al[4];
                ah[0] = *reinterpret_cast<const uint32_t*>(ap);
                ah[1] = *reinterpret_cast<const uint32_t*>(ap + 8*SAS);
                ah[2] = *reinterpret_cast<const uint32_t*>(ap + 8);
                ah[3] = *reinterpret_cast<const uint32_t*>(ap + 8*SAS + 8);
                al[0] = *reinterpret_cast<const uint32_t*>(lp);
                al[1] = *reinterpret_cast<const uint32_t*>(lp + 8*SAS);
                al[2] = *reinterpret_cast<const uint32_t*>(lp + 8);
                al[3] = *reinterpret_cast<const uint32_t*>(lp + 8*SAS + 8);
#pragma unroll
                for (int ni = 0; ni < 4; ni++) {
                    mma16816(acc[mi][ni], ah, bh[ni]);
                    mma16816(acc[mi][ni], ah, bl[ni]);
                    mma16816(acc[mi][ni], al, bh[ni]);
                }
            }
        }
        __syncthreads();
    }

    // ---- Epilogue ----
    const int rbase = row0 + wr0;
    const int cbase = col0 + wc0;

    if (MODE == 3) {
#pragma unroll
        for (int mi = 0; mi < 4; mi++)
#pragma unroll
            for (int ni = 0; ni < 4; ni++) {
                int r = rbase + mi*16 + g;
                int c = cbase + ni*8 + 2*tig;
                *reinterpret_cast<float2*>(&C[(size_t)r * DDIM + c]) =
                    make_float2(acc[mi][ni][0], acc[mi][ni][1]);
                *reinterpret_cast<float2*>(&C[(size_t)(r + 8) * DDIM + c]) =
                    make_float2(acc[mi][ni][2], acc[mi][ni][3]);
            }
    } else if (MODE == 2) {
#pragma unroll
        for (int mi = 0; mi < 4; mi++)
#pragma unroll
            for (int ni = 0; ni < 4; ni++) {
                int r = rbase + mi*16 + g;
                int c = cbase + ni*8 + 2*tig;
                store_split2(Dhi, Dlo, (size_t)r * DDIM + c, acc[mi][ni][0], acc[mi][ni][1]);
                store_split2(Dhi, Dlo, (size_t)(r + 8) * DDIM + c, acc[mi][ni][2], acc[mi][ni][3]);
            }
    } else {
        // RoPE (+ scale for Q) then split
        const float scale = (MODE == 0) ? 0.125f : 1.0f;
        float inv[4];
#pragma unroll
        for (int ni = 0; ni < 4; ni++) {
            int c = cbase + ni*8 + 2*tig;
            inv[ni] = exp2f(-(float)((c & 63) >> 1) * (13.287712379549449f / 32.0f));
        }
#pragma unroll
        for (int mi = 0; mi < 4; mi++) {
            int r = rbase + mi*16 + g;
            float pv0 = (float)tp[r & (SEQ - 1)];
            float pv1 = (float)tp[(r + 8) & (SEQ - 1)];
#pragma unroll
            for (int ni = 0; ni < 4; ni++) {
                int c = cbase + ni*8 + 2*tig;
                float sn, cs;
                sincosf(pv0 * inv[ni], &sn, &cs);
                cs *= scale; sn *= scale;
                store_split2(Dhi, Dlo, (size_t)r * DDIM + c,
                             cs*acc[mi][ni][0] - sn*acc[mi][ni][1],
                             sn*acc[mi][ni][0] + cs*acc[mi][ni][1]);
                sincosf(pv1 * inv[ni], &sn, &cs);
                cs *= scale; sn *= scale;
                store_split2(Dhi, Dlo, (size_t)(r + 8) * DDIM + c,
                             cs*acc[mi][ni][2] - sn*acc[mi][ni][3],
                             sn*acc[mi][ni][2] + cs*acc[mi][ni][3]);
            }
        }
    }
}

__global__ __launch_bounds__(256)
void qkv_hmma_kernel(const int* __restrict__ tp)
{
    const int z = blockIdx.z;
    const size_t wo = (size_t)z * DDIM * DDIM;
    const int row0 = blockIdx.y * 128, col0 = blockIdx.x * 128;
    if (z == 0)
        hmma_gemm_body<0>(g_xhi, g_xlo, g_whi + wo, g_wlo + wo, nullptr, g_qhi, g_qlo, tp, row0, col0);
    else if (z == 1)
        hmma_gemm_body<1>(g_xhi, g_xlo, g_whi + wo, g_wlo + wo, nullptr, g_khi, g_klo, tp, row0, col0);
    else
        hmma_gemm_body<2>(g_xhi, g_xlo, g_whi + wo, g_wlo + wo, nullptr, g_vhi, g_vlo, tp, row0, col0);
}

__global__ __launch_bounds__(256)
void out_hmma_kernel(float* __restrict__ Out)
{
    const size_t wo = 3ull * DDIM * DDIM;
    hmma_gemm_body<3>(g_ohi, g_olo, g_whi + wo, g_wlo + wo, Out, nullptr, nullptr, nullptr,
                      blockIdx.y * 128, blockIdx.x * 128);
}

// ---------------------------------------------------------------------------
// fp32 -> (bf16 hi, bf16 lo) split kernels (x and weights only)
// ---------------------------------------------------------------------------
__device__ __forceinline__ void split4_store(const float4 v,
                                             __nv_bfloat16* hi, __nv_bfloat16* lo, size_t i)
{
    float f[4] = {v.x, v.y, v.z, v.w};
    unsigned short H[4], L[4];
#pragma unroll
    for (int j = 0; j < 4; j++) {
        __nv_bfloat16 h = __float2bfloat16_rn(f[j]);
        __nv_bfloat16 l = __float2bfloat16_rn(f[j] - __bfloat162float(h));
        H[j] = __bfloat16_as_ushort(h);
        L[j] = __bfloat16_as_ushort(l);
    }
    reinterpret_cast<ushort4*>(hi)[i] = make_ushort4(H[0], H[1], H[2], H[3]);
    reinterpret_cast<ushort4*>(lo)[i] = make_ushort4(L[0], L[1], L[2], L[3]);
}

__global__ __launch_bounds__(256)
void split_x_kernel(const float* __restrict__ in)
{
    size_t i = (size_t)blockIdx.x * 256 + threadIdx.x;
    split4_store(reinterpret_cast<const float4*>(in)[i], g_xhi, g_xlo, i);
}

__global__ __launch_bounds__(256)
void split_w_kernel(const float* __restrict__ wq, const float* __restrict__ wk,
                    const float* __restrict__ wv, const float* __restrict__ wo)
{
    const int z = blockIdx.z;
    const float* src = (z == 0) ? wq : (z == 1) ? wk : (z == 2) ? wv : wo;
    __nv_bfloat16* hi = g_whi + (size_t)z * DDIM * DDIM;
    __nv_bfloat16* lo = g_wlo + (size_t)z * DDIM * DDIM;
    size_t i = (size_t)blockIdx.x * 256 + threadIdx.x;
    split4_store(reinterpret_cast<const float4*>(src)[i], hi, lo, i);
}

// ---------------------------------------------------------------------------
// Causal flash attention, HMMA, bf16 hi/lo inputs, cp.async double-buffered K/V.
// CTA: 128 query rows, 8 warps. Key tiles of 64. V kept row-major; P·V B-frags
// come from ldmatrix.x4.trans.
// ---------------------------------------------------------------------------
#define AST 72                        // smem row stride (64 + 8 pad) bf16
#define A_Q_ELEMS   (128*AST)         // 9216 per Q array
#define A_KV_ELEMS  (64*AST)          // 4608 per K/V array
#define A_STAGE0    (2*A_Q_ELEMS)     // 18432
#define A_STAGE_SZ  (4*A_KV_ELEMS)    // 18432
#define ATT_SMEM    ((A_STAGE0 + 2*A_STAGE_SZ) * 2)   // 110592 bytes

__device__ __forceinline__ void kv_issue(size_t gbase, int kt, int st,
                                         uint32_t smb, int tid)
{
#pragma unroll
    for (int l = 0; l < 8; l++) {
        int a = l >> 1;
        int j = tid + (l & 1) * 256;
        int r = j >> 3, c = j & 7;
        const __nv_bfloat16* src = (a == 0) ? g_khi : (a == 1) ? g_klo
                                 : (a == 2) ? g_vhi : g_vlo;
        size_t go = gbase + (size_t)(kt * 64 + r) * DDIM + c * 8;
        uint32_t so = smb + (uint32_t)(A_STAGE0 + st * A_STAGE_SZ + a * A_KV_ELEMS
                                       + r * AST + c * 8) * 2;
        cp16(so, src + go);
    }
}

__global__ __launch_bounds__(256)
void attn_hmma_kernel()
{
    extern __shared__ char dynsm[];
    __nv_bfloat16* sm = reinterpret_cast<__nv_bfloat16*>(dynsm);
    const uint32_t smb = smem_u32(sm);

    __nv_bfloat16* sQhi = sm;
    __nv_bfloat16* sQlo = sm + A_Q_ELEMS;

    const int tid  = threadIdx.x;
    const int warp = tid >> 5;
    const int lane = tid & 31;
    const int g    = lane >> 2;
    const int tig  = lane & 3;

    const int q0 = blockIdx.x * 128;
    const int bh = blockIdx.y;
    const size_t gbase = (size_t)(bh >> 4) * SEQ * DDIM + (bh & 15) * DK;

    // Q tile via cp.async (grouped with first K/V stage)
#pragma unroll
    for (int l = 0; l < 8; l++) {
        int a = l >> 2;                    // 0: hi, 1: lo
        int j = tid + (l & 3) * 256;
        int r = j >> 3, c = j & 7;
        const __nv_bfloat16* src = a ? g_qlo : g_qhi;
        size_t go = gbase + (size_t)(q0 + r) * DDIM + c * 8;
        uint32_t so = smb + (uint32_t)(a * A_Q_ELEMS + r * AST + c * 8) * 2;
        cp16(so, src + go);
    }
    kv_issue(gbase, 0, 0, smb, tid);
    CP_COMMIT();

    const int r0 = warp * 16;
    float m0 = -1e30f, m1 = -1e30f, l0 = 0.f, l1 = 0.f;
    float of[8][4];
#pragma unroll
    for (int ni = 0; ni < 8; ni++)
#pragma unroll
        for (int r = 0; r < 4; r++) of[ni][r] = 0.f;

    const int diag0 = q0 >> 6;
    const int ktmax = diag0 + 1;

    for (int kt = 0; kt <= ktmax; kt++) {
        if (kt < ktmax) kv_issue(gbase, kt + 1, (kt + 1) & 1, smb, tid);
        CP_COMMIT();
        if (kt < ktmax) { CP_WAIT(1); } else { CP_WAIT(0); }
        __syncthreads();

        const int stg = (kt & 1);
        const __nv_bfloat16* sKhi = sm + A_STAGE0 + stg * A_STAGE_SZ;
        const __nv_bfloat16* sKlo = sKhi + A_KV_ELEMS;
        const uint32_t vhi_base = smb + (uint32_t)(A_STAGE0 + stg * A_STAGE_SZ + 2 * A_KV_ELEMS) * 2;
        const uint32_t vlo_base = vhi_base + (uint32_t)A_KV_ELEMS * 2;

        // ---- S = Q K^T ----
        float sf[8][4];
#pragma unroll
        for (int ni = 0; ni < 8; ni++)
#pragma unroll
            for (int r = 0; r < 4; r++) sf[ni][r] = 0.f;

#pragma unroll
        for (int ks = 0; ks < 4; ks++) {
            const int kc = ks * 16 + 2 * tig;
            const __nv_bfloat16* qp = &sQhi[(r0 + g)*AST + kc];
            const __nv_bfloat16* ql = &sQlo[(r0 + g)*AST + kc];
            uint32_t ah[4], al[4];
            ah[0] = *reinterpret_cast<const uint32_t*>(qp);
            ah[1] = *reinterpret_cast<const uint32_t*>(qp + 8*AST);
            ah[2] = *reinterpret_cast<const uint32_t*>(qp + 8);
            ah[3] = *reinterpret_cast<const uint32_t*>(qp + 8*AST + 8);
            al[0] = *reinterpret_cast<const uint32_t*>(ql);
            al[1] = *reinterpret_cast<const uint32_t*>(ql + 8*AST);
            al[2] = *reinterpret_cast<const uint32_t*>(ql + 8);
            al[3] = *reinterpret_cast<const uint32_t*>(ql + 8*AST + 8);
#pragma unroll
            for (int ni = 0; ni < 8; ni++) {
                const __nv_bfloat16* kp = &sKhi[(ni*8 + g)*AST + kc];
                const __nv_bfloat16* kl = &sKlo[(ni*8 + g)*AST + kc];
                uint32_t bhr[2], blr[2];
                bhr[0] = *reinterpret_cast<const uint32_t*>(kp);
                bhr[1] = *reinterpret_cast<const uint32_t*>(kp + 8);
                blr[0] = *reinterpret_cast<const uint32_t*>(kl);
                blr[1] = *reinterpret_cast<const uint32_t*>(kl + 8);
                mma16816(sf[ni], ah, bhr);
                mma16816(sf[ni], ah, blr);
                mma16816(sf[ni], al, bhr);
            }
        }

        // ---- causal mask ----
        if (kt >= diag0) {
            const int rowg0 = q0 + r0 + g;
#pragma unroll
            for (int ni = 0; ni < 8; ni++) {
                int c0 = kt*64 + ni*8 + 2*tig;
                if (c0     > rowg0)     sf[ni][0] = -1e30f;
                if (c0 + 1 > rowg0)     sf[ni][1] = -1e30f;
                if (c0     > rowg0 + 8) sf[ni][2] = -1e30f;
                if (c0 + 1 > rowg0 + 8) sf[ni][3] = -1e30f;
            }
        }

        // ---- online softmax ----
        float tm0 = -1e30f, tm1 = -1e30f;
#pragma unroll
        for (int ni = 0; ni < 8; ni++) {
            tm0 = fmaxf(tm0, fmaxf(sf[ni][0], sf[ni][1]));
            tm1 = fmaxf(tm1, fmaxf(sf[ni][2], sf[ni][3]));
        }
        tm0 = fmaxf(tm0, __shfl_xor_sync(0xFFFFFFFF, tm0, 1));
        tm0 = fmaxf(tm0, __shfl_xor_sync(0xFFFFFFFF, tm0, 2));
        tm1 = fmaxf(tm1, __shfl_xor_sync(0xFFFFFFFF, tm1, 1));
        tm1 = fmaxf(tm1, __shfl_xor_sync(0xFFFFFFFF, tm1, 2));

        float mn0 = fmaxf(m0, tm0);
        float mn1 = fmaxf(m1, tm1);
        float a0 = __expf(m0 - mn0);
        float a1 = __expf(m1 - mn1);
        l0 *= a0; l1 *= a1;
#pragma unroll
        for (int ni = 0; ni < 8; ni++) {
            of[ni][0] *= a0; of[ni][1] *= a0;
            of[ni][2] *= a1; of[ni][3] *= a1;
        }
#pragma unroll
        for (int ni = 0; ni < 8; ni++) {
            float p0 = __expf(sf[ni][0] - mn0);
            float p1 = __expf(sf[ni][1] - mn0);
            float p2 = __expf(sf[ni][2] - mn1);
            float p3 = __expf(sf[ni][3] - mn1);
            sf[ni][0] = p0; sf[ni][1] = p1; sf[ni][2] = p2; sf[ni][3] = p3;
            l0 += p0 + p1;  l1 += p2 + p3;
        }
        m0 = mn0; m1 = mn1;

        // ---- O += P V  (V row-major; B-frags via ldmatrix.trans) ----
        const uint32_t lrow = (uint32_t)(lane & 15);
        const uint32_t lcol = (uint32_t)((lane & 16) >> 1);
#pragma unroll
        for (int kb = 0; kb < 4; kb++) {
            uint32_t ph[4], pl[4];
            float f00 = sf[2*kb][0],   f01 = sf[2*kb][1];
            float f10 = sf[2*kb][2],   f11 = sf[2*kb][3];
            float f20 = sf[2*kb+1][0], f21 = sf[2*kb+1][1];
            float f30 = sf[2*kb+1][2], f31 = sf[2*kb+1][3];
            ph[0] = pack_bf16(f00, f01);
            ph[1] = pack_bf16(f10, f11);
            ph[2] = pack_bf16(f20, f21);
            ph[3] = pack_bf16(f30, f31);
            pl[0] = pack_bf16(f00 - __bfloat162float(__float2bfloat16_rn(f00)),
                              f01 - __bfloat162float(__float2bfloat16_rn(f01)));
            pl[1] = pack_bf16(f10 - __bfloat162float(__float2bfloat16_rn(f10)),
                              f11 - __bfloat162float(__float2bfloat16_rn(f11)));
            pl[2] = pack_bf16(f20 - __bfloat162float(__float2bfloat16_rn(f20)),
                              f21 - __bfloat162float(__float2bfloat16_rn(f21)));
            pl[3] = pack_bf16(f30 - __bfloat162float(__float2bfloat16_rn(f30)),
                              f31 - __bfloat162float(__float2bfloat16_rn(f31)));

            const uint32_t roff = (uint32_t)(kb * 16 + lrow) * AST;
#pragma unroll
            for (int nip = 0; nip < 4; nip++) {
                uint32_t addr = (roff + (uint32_t)(nip * 16) + lcol) * 2;
                uint32_t vh[4], vl[4];
                ldsm_x4_t(vh, vhi_base + addr);
                ldsm_x4_t(vl, vlo_base + addr);
                mma16816(of[2*nip],     ph, vh);
                mma16816(of[2*nip],     ph, vl);
                mma16816(of[2*nip],     pl, vh);
                mma16816(of[2*nip + 1], ph, vh + 2);
                mma16816(of[2*nip + 1], ph, vl + 2);
                mma16816(of[2*nip + 1], pl, vh + 2);
            }
        }
        __syncthreads();
    }

    // Final: reduce l over quad, normalize, split-store to g_ohi/g_olo
    l0 += __shfl_xor_sync(0xFFFFFFFF, l0, 1);
    l0 += __shfl_xor_sync(0xFFFFFFFF, l0, 2);
    l1 += __shfl_xor_sync(0xFFFFFFFF, l1, 1);
    l1 += __shfl_xor_sync(0xFFFFFFFF, l1, 2);
    const float inv0 = 1.0f / l0;
    const float inv1 = 1.0f / l1;

    const int rowg = q0 + r0 + g;
#pragma unroll
    for (int ni = 0; ni < 8; ni++) {
        int c = ni*8 + 2*tig;
        store_split2(g_ohi, g_olo, gbase + (size_t)rowg * DDIM + c,
                     of[ni][0] * inv0, of[ni][1] * inv0);
        store_split2(g_ohi, g_olo, gbase + (size_t)(rowg + 8) * DDIM + c,
                     of[ni][2] * inv1, of[ni][3] * inv1);
    }
}

// ---------------------------------------------------------------------------
extern "C" void kernel_launch(void* const* d_in, const int* in_sizes, int n_in,
                              void* d_out, int out_size)
{
    const float* x  = (const float*)d_in[0];
    const int*   tp = (const int*)  d_in[1];
    const float* wq = (const float*)d_in[2];
    const float* wk = (const float*)d_in[3];
    const float* wv = (const float*)d_in[4];
    const float* wo = (const float*)d_in[5];
    float* out = (float*)d_out;

    cudaFuncSetAttribute(qkv_hmma_kernel, cudaFuncAttributeMaxDynamicSharedMemorySize, GEMM_SMEM);
    cudaFuncSetAttribute(out_hmma_kernel, cudaFuncAttributeMaxDynamicSharedMemorySize, GEMM_SMEM);
    cudaFuncSetAttribute(attn_hmma_kernel, cudaFuncAttributeMaxDynamicSharedMemorySize, ATT_SMEM);

    // Split inputs to bf16 hi/lo
    split_x_kernel<<<(MTOT*DDIM/4)/256, 256>>>(x);
    split_w_kernel<<<dim3((DDIM*DDIM/4)/256, 1, 4), 256>>>(wq, wk, wv, wo);

    // QKV projections (HMMA) with fused RoPE + scale + bf16 split epilogue
    qkv_hmma_kernel<<<dim3(DDIM/128, MTOT/128, 3), 256, GEMM_SMEM>>>(tp);

    // Causal flash attention (HMMA), writes bf16 hi/lo directly
    attn_hmma_kernel<<<dim3(SEQ/128, BATCH*NHEAD), 256, ATT_SMEM>>>();

    // Output projection (HMMA), fp32 store
    out_hmma_kernel<<<dim3(DDIM/128, MTOT/128, 1), 256, GEMM_SMEM>>>(out);
}